// round 6
// baseline (speedup 1.0000x reference)
#include <cuda_runtime.h>
#include <cuda_fp16.h>

// TriMip encoding v3: 3 planes, 8 mip levels (512->4), 16 features.
//  - K1: fused  fm -> fp16 level0  +  fp32/fp16 level1 (reads fm once)
//  - K2: levels 2..7 flat box-mean from fp32 level1 (warp-coop for big boxes)
//  - S : persistent sampler; levels 5..7 staged in shared memory (32.3 KB),
//        generic per-lane addressing picks smem vs global.

#define NLV 8

// fp32 level-1 scratch: 3*256*256*16 floats = 12.6 MB
__device__ float g_l1[3145728];
// fp16 pyramid, levels 0..7: 16,776,960 halves (~33.5 MB)
__device__ __half g_pyrh[16776960];

// half offsets of fp16 levels inside g_pyrh
__constant__ int c_offh[8] = {0, 12582912, 15728640, 16515072, 16711680,
                              16760832, 16773120, 16776192};

// ---------------------------------------------------------------------------
// K1: one thread per level-1 quad (3*256*256*4 threads).
// Reads 2x2 fm quads (fp32), writes 4 fp16 level-0 quads, 1 fp32 + 1 fp16
// level-1 quad.
__global__ void __launch_bounds__(256) k1_l0_l1(const float* __restrict__ fm) {
    int t = blockIdx.x * blockDim.x + threadIdx.x;
    const int total = 3 * 256 * 256 * 4;
    if (t >= total) return;
    int q   = t & 3;
    int idx = t >> 2;
    int xo  = idx & 255; idx >>= 8;
    int yo  = idx & 255;
    int pl  = idx >> 8;

    const float4* src = (const float4*)fm;
    int y0 = 2 * yo, x0 = 2 * xo;
    long b00 = ((long)(pl * 512 + y0) * 512 + x0) * 4 + q;
    float4 a = __ldg(src + b00);
    float4 b = __ldg(src + b00 + 4);
    float4 c = __ldg(src + b00 + 512 * 4);
    float4 d = __ldg(src + b00 + 512 * 4 + 4);

    uint2* l0h = (uint2*)g_pyrh;   // quad = 4 halves = 8B
    uint2 pa, pb, pc, pd;
    #define PACKQ(dst, v) { __half2 _h0 = __floats2half2_rn((v).x, (v).y); \
                            __half2 _h1 = __floats2half2_rn((v).z, (v).w); \
                            (dst).x = *(unsigned*)&_h0; (dst).y = *(unsigned*)&_h1; }
    PACKQ(pa, a); PACKQ(pb, b); PACKQ(pc, c); PACKQ(pd, d);
    l0h[b00]               = pa;
    l0h[b00 + 4]           = pb;
    l0h[b00 + 512 * 4]     = pc;
    l0h[b00 + 512 * 4 + 4] = pd;

    float4 o;
    o.x = (a.x + b.x + c.x + d.x) * 0.25f;
    o.y = (a.y + b.y + c.y + d.y) * 0.25f;
    o.z = (a.z + b.z + c.z + d.z) * 0.25f;
    o.w = (a.w + b.w + c.w + d.w) * 0.25f;

    long l1i = ((long)(pl * 256 + yo) * 256 + xo) * 4 + q;
    ((float4*)g_l1)[l1i] = o;
    uint2 po; PACKQ(po, o);
    ((uint2*)(g_pyrh + c_offh[1]))[l1i] = po;
    #undef PACKQ
}

// ---------------------------------------------------------------------------
// K2: levels 2..7 from fp32 level1 by flat box mean.
// Per-thread items: levels 2..4 quads (box <= 64 reads).
// Per-warp items:   levels 5..7 quads (lanes split the box, shfl reduce).
__global__ void __launch_bounds__(256) k2_levels(void) {
    const int PT_L2 = 3 * 128 * 128 * 4;   // 196608
    const int PT_L3 = 3 * 64 * 64 * 4;     // 49152
    const int PT_L4 = 3 * 32 * 32 * 4;     // 12288
    const int PT_TOTAL = PT_L2 + PT_L3 + PT_L4;          // 258048
    const int PW_L5 = 3 * 16 * 16 * 4;     // 3072
    const int PW_L6 = 3 * 8 * 8 * 4;       // 768
    const int PW_L7 = 3 * 4 * 4 * 4;       // 192

    int t = blockIdx.x * blockDim.x + threadIdx.x;
    const float4* l1 = (const float4*)g_l1;

    if (t < PT_TOTAL) {
        int l, rem = t;
        if (rem < PT_L2) l = 2;
        else if (rem < PT_L2 + PT_L3) { l = 3; rem -= PT_L2; }
        else { l = 4; rem -= PT_L2 + PT_L3; }
        int S = 512 >> l;
        int B = 1 << (l - 1);          // box side in level-1 texels
        int q = rem & 3; int idx = rem >> 2;
        int x = idx % S; idx /= S;
        int y = idx % S;
        int pl = idx / S;

        float4 acc = make_float4(0.f, 0.f, 0.f, 0.f);
        int ybase = y * B, xbase = x * B;
        for (int by = 0; by < B; by++) {
            long row = ((long)(pl * 256 + ybase + by) * 256 + xbase) * 4 + q;
            for (int bx = 0; bx < B; bx++) {
                float4 v = __ldg(l1 + row + bx * 4);
                acc.x += v.x; acc.y += v.y; acc.z += v.z; acc.w += v.w;
            }
        }
        float inv = 1.0f / (float)(B * B);
        acc.x *= inv; acc.y *= inv; acc.z *= inv; acc.w *= inv;
        __half2 h0 = __floats2half2_rn(acc.x, acc.y);
        __half2 h1 = __floats2half2_rn(acc.z, acc.w);
        uint2 po; po.x = *(unsigned*)&h0; po.y = *(unsigned*)&h1;
        ((uint2*)(g_pyrh + c_offh[l]))[((long)(pl * S + y) * S + x) * 4 + q] = po;
        return;
    }

    // warp items
    int w = (t - PT_TOTAL) >> 5;
    int lane = t & 31;
    int l, rem = w;
    if (rem < PW_L5) l = 5;
    else if (rem < PW_L5 + PW_L6) { l = 6; rem -= PW_L5; }
    else if (rem < PW_L5 + PW_L6 + PW_L7) { l = 7; rem -= PW_L5 + PW_L6; }
    else return;

    int S = 512 >> l;
    int B = 1 << (l - 1);              // 16 / 32 / 64
    int nbox = B * B;
    int q = rem & 3; int idx = rem >> 2;
    int x = idx % S; idx /= S;
    int y = idx % S;
    int pl = idx / S;

    float4 acc = make_float4(0.f, 0.f, 0.f, 0.f);
    for (int j = lane; j < nbox; j += 32) {
        int by = j / B, bx = j - by * B;
        long e = ((long)(pl * 256 + y * B + by) * 256 + x * B + bx) * 4 + q;
        float4 v = __ldg(l1 + e);
        acc.x += v.x; acc.y += v.y; acc.z += v.z; acc.w += v.w;
    }
    #pragma unroll
    for (int off = 16; off > 0; off >>= 1) {
        acc.x += __shfl_down_sync(0xffffffffu, acc.x, off);
        acc.y += __shfl_down_sync(0xffffffffu, acc.y, off);
        acc.z += __shfl_down_sync(0xffffffffu, acc.z, off);
        acc.w += __shfl_down_sync(0xffffffffu, acc.w, off);
    }
    if (lane == 0) {
        float inv = 1.0f / (float)nbox;
        acc.x *= inv; acc.y *= inv; acc.z *= inv; acc.w *= inv;
        __half2 h0 = __floats2half2_rn(acc.x, acc.y);
        __half2 h1 = __floats2half2_rn(acc.z, acc.w);
        uint2 po; po.x = *(unsigned*)&h0; po.y = *(unsigned*)&h1;
        ((uint2*)(g_pyrh + c_offh[l]))[((long)(pl * S + y) * S + x) * 4 + q] = po;
    }
}

// ---------------------------------------------------------------------------
// Sampler: persistent grid-stride, 6 work items per point
// (3 planes x 2 feature-halves). Levels 5..7 staged in shared memory.
#define STOP_HALVES 16128   // 3*(16*16 + 8*8 + 4*4)*16

__global__ void __launch_bounds__(256, 5) trimip_sample(
    const float* __restrict__ x,
    const float* __restrict__ level,
    float* __restrict__ out,
    int N)
{
    __shared__ __align__(16) __half s_top[STOP_HALVES];

    // fill smem with levels 5..7 (contiguous in g_pyrh starting at c_offh[5])
    {
        const float4* src = (const float4*)(g_pyrh + c_offh[5]);
        float4* dst = (float4*)s_top;
        for (int i = threadIdx.x; i < STOP_HALVES / 8; i += blockDim.x)
            dst[i] = __ldg(src + i);
    }
    __syncthreads();

    int total = N * 6;
    int stride = gridDim.x * blockDim.x;

    for (int t = blockIdx.x * blockDim.x + threadIdx.x; t < total; t += stride) {
        int n = t / 6;
        int r = t - n * 6;
        int p = r >> 1;     // plane
        int h = r & 1;      // feature half (8 feats)

        float xc0 = __ldg(&x[3 * n + 0]);
        float xc1 = __ldg(&x[3 * n + 1]);
        float xc2 = __ldg(&x[3 * n + 2]);
        float u = (p == 0) ? xc1 : xc0;
        float v = (p == 2) ? xc1 : xc2;

        float lvl = fminf(fmaxf(__ldg(&level[n]), 0.0f), (float)(NLV - 1));
        int   l0  = min((int)lvl, NLV - 2);
        float fr  = lvl - (float)l0;

        float acc[8] = {0.f, 0.f, 0.f, 0.f, 0.f, 0.f, 0.f, 0.f};

        #pragma unroll
        for (int k = 0; k < 2; k++) {
            int   l = l0 + k;
            float w = k ? fr : (1.0f - fr);
            int   S = 512 >> l;

            // generic pointer: smem for levels >= 5, global otherwise
            const __half* lvbase = (l >= 5)
                ? (const __half*)s_top + (c_offh[l] - c_offh[5])
                : (const __half*)g_pyrh + c_offh[l];
            const __half* base = lvbase + (long)p * S * S * 16 + h * 8;

            float px = u * (float)S - 0.5f;
            float py = v * (float)S - 0.5f;
            float fx = floorf(px);
            float fy = floorf(py);
            int ix0 = (int)fx;
            int iy0 = (int)fy;
            int ix1 = min(ix0 + 1, S - 1);
            int iy1 = min(iy0 + 1, S - 1);
            ix0 = max(ix0, 0);
            iy0 = max(iy0, 0);
            float ax = px - fx;
            float ay = py - fy;

            float4 v00 = *(const float4*)(base + (iy0 * S + ix0) * 16);
            float4 v10 = *(const float4*)(base + (iy0 * S + ix1) * 16);
            float4 v01 = *(const float4*)(base + (iy1 * S + ix0) * 16);
            float4 v11 = *(const float4*)(base + (iy1 * S + ix1) * 16);

            float w00 = w * (1.0f - ax) * (1.0f - ay);
            float w10 = w * ax * (1.0f - ay);
            float w01 = w * (1.0f - ax) * ay;
            float w11 = w * ax * ay;

            #define ACCQ(wgt, raw) { const __half2* _hp = (const __half2*)&(raw); \
                float2 _f0 = __half22float2(_hp[0]); float2 _f1 = __half22float2(_hp[1]); \
                float2 _f2 = __half22float2(_hp[2]); float2 _f3 = __half22float2(_hp[3]); \
                acc[0] = fmaf(wgt, _f0.x, acc[0]); acc[1] = fmaf(wgt, _f0.y, acc[1]); \
                acc[2] = fmaf(wgt, _f1.x, acc[2]); acc[3] = fmaf(wgt, _f1.y, acc[3]); \
                acc[4] = fmaf(wgt, _f2.x, acc[4]); acc[5] = fmaf(wgt, _f2.y, acc[5]); \
                acc[6] = fmaf(wgt, _f3.x, acc[6]); acc[7] = fmaf(wgt, _f3.y, acc[7]); }
            ACCQ(w00, v00); ACCQ(w10, v10); ACCQ(w01, v01); ACCQ(w11, v11);
            #undef ACCQ
        }

        float4* o = (float4*)(out + (long)n * 48 + p * 16 + h * 8);
        o[0] = make_float4(acc[0], acc[1], acc[2], acc[3]);
        o[1] = make_float4(acc[4], acc[5], acc[6], acc[7]);
    }
}

// ---------------------------------------------------------------------------
extern "C" void kernel_launch(void* const* d_in, const int* in_sizes, int n_in,
                              void* d_out, int out_size) {
    const float* x     = (const float*)d_in[0];
    const float* level = (const float*)d_in[1];
    const float* fm    = (const float*)d_in[2];
    float* out = (float*)d_out;
    int N = in_sizes[0] / 3;

    // K1: level 0 convert + level 1 build (single pass over fm)
    {
        int total = 3 * 256 * 256 * 4;
        k1_l0_l1<<<(total + 255) / 256, 256>>>(fm);
    }
    // K2: levels 2..7
    {
        int total_threads = 258048 + (3072 + 768 + 192) * 32;  // 387072
        k2_levels<<<(total_threads + 255) / 256, 256>>>();
    }
    // S: persistent sampler
    trimip_sample<<<148 * 5, 256>>>(x, level, out, N);
}

// round 9
// speedup vs baseline: 1.0735x; 1.0735x over previous
#include <cuda_runtime.h>
#include <cuda_fp16.h>

// TriMip encoding v4: fused 2-kernel pyramid build (from v3) + v2 sampler
// (plain __ldg gathers, no smem, no persistent occupancy cap).

#define NLV 8

// fp32 level-1 scratch: 3*256*256*16 floats = 12.6 MB
__device__ float g_l1[3145728];
// fp16 pyramid, levels 0..7: 16,776,960 halves (~33.5 MB)
__device__ __half g_pyrh[16776960];

// half offsets of fp16 levels inside g_pyrh
__constant__ int c_offh[8] = {0, 12582912, 15728640, 16515072, 16711680,
                              16760832, 16773120, 16776192};

// ---------------------------------------------------------------------------
// K1: one thread per level-1 quad (3*256*256*4 threads).
// Reads 2x2 fm quads (fp32), writes 4 fp16 level-0 quads, 1 fp32 + 1 fp16
// level-1 quad.
__global__ void __launch_bounds__(256) k1_l0_l1(const float* __restrict__ fm) {
    int t = blockIdx.x * blockDim.x + threadIdx.x;
    const int total = 3 * 256 * 256 * 4;
    if (t >= total) return;
    int q   = t & 3;
    int idx = t >> 2;
    int xo  = idx & 255; idx >>= 8;
    int yo  = idx & 255;
    int pl  = idx >> 8;

    const float4* src = (const float4*)fm;
    int y0 = 2 * yo, x0 = 2 * xo;
    long b00 = ((long)(pl * 512 + y0) * 512 + x0) * 4 + q;
    float4 a = __ldg(src + b00);
    float4 b = __ldg(src + b00 + 4);
    float4 c = __ldg(src + b00 + 512 * 4);
    float4 d = __ldg(src + b00 + 512 * 4 + 4);

    uint2* l0h = (uint2*)g_pyrh;   // quad = 4 halves = 8B
    uint2 pa, pb, pc, pd;
    #define PACKQ(dst, v) { __half2 _h0 = __floats2half2_rn((v).x, (v).y); \
                            __half2 _h1 = __floats2half2_rn((v).z, (v).w); \
                            (dst).x = *(unsigned*)&_h0; (dst).y = *(unsigned*)&_h1; }
    PACKQ(pa, a); PACKQ(pb, b); PACKQ(pc, c); PACKQ(pd, d);
    l0h[b00]               = pa;
    l0h[b00 + 4]           = pb;
    l0h[b00 + 512 * 4]     = pc;
    l0h[b00 + 512 * 4 + 4] = pd;

    float4 o;
    o.x = (a.x + b.x + c.x + d.x) * 0.25f;
    o.y = (a.y + b.y + c.y + d.y) * 0.25f;
    o.z = (a.z + b.z + c.z + d.z) * 0.25f;
    o.w = (a.w + b.w + c.w + d.w) * 0.25f;

    long l1i = ((long)(pl * 256 + yo) * 256 + xo) * 4 + q;
    ((float4*)g_l1)[l1i] = o;
    uint2 po; PACKQ(po, o);
    ((uint2*)(g_pyrh + c_offh[1]))[l1i] = po;
    #undef PACKQ
}

// ---------------------------------------------------------------------------
// K2: levels 2..7 from fp32 level1 by flat box mean.
// Per-thread items: levels 2..4 quads; per-warp items: levels 5..7 quads.
__global__ void __launch_bounds__(256) k2_levels(void) {
    const int PT_L2 = 3 * 128 * 128 * 4;   // 196608
    const int PT_L3 = 3 * 64 * 64 * 4;     // 49152
    const int PT_L4 = 3 * 32 * 32 * 4;     // 12288
    const int PT_TOTAL = PT_L2 + PT_L3 + PT_L4;          // 258048
    const int PW_L5 = 3 * 16 * 16 * 4;     // 3072
    const int PW_L6 = 3 * 8 * 8 * 4;       // 768
    const int PW_L7 = 3 * 4 * 4 * 4;       // 192

    int t = blockIdx.x * blockDim.x + threadIdx.x;
    const float4* l1 = (const float4*)g_l1;

    if (t < PT_TOTAL) {
        int l, rem = t;
        if (rem < PT_L2) l = 2;
        else if (rem < PT_L2 + PT_L3) { l = 3; rem -= PT_L2; }
        else { l = 4; rem -= PT_L2 + PT_L3; }
        int S = 512 >> l;
        int B = 1 << (l - 1);          // box side in level-1 texels
        int q = rem & 3; int idx = rem >> 2;
        int x = idx % S; idx /= S;
        int y = idx % S;
        int pl = idx / S;

        float4 acc = make_float4(0.f, 0.f, 0.f, 0.f);
        int ybase = y * B, xbase = x * B;
        for (int by = 0; by < B; by++) {
            long row = ((long)(pl * 256 + ybase + by) * 256 + xbase) * 4 + q;
            for (int bx = 0; bx < B; bx++) {
                float4 v = __ldg(l1 + row + bx * 4);
                acc.x += v.x; acc.y += v.y; acc.z += v.z; acc.w += v.w;
            }
        }
        float inv = 1.0f / (float)(B * B);
        acc.x *= inv; acc.y *= inv; acc.z *= inv; acc.w *= inv;
        __half2 h0 = __floats2half2_rn(acc.x, acc.y);
        __half2 h1 = __floats2half2_rn(acc.z, acc.w);
        uint2 po; po.x = *(unsigned*)&h0; po.y = *(unsigned*)&h1;
        ((uint2*)(g_pyrh + c_offh[l]))[((long)(pl * S + y) * S + x) * 4 + q] = po;
        return;
    }

    // warp items
    int w = (t - PT_TOTAL) >> 5;
    int lane = t & 31;
    int l, rem = w;
    if (rem < PW_L5) l = 5;
    else if (rem < PW_L5 + PW_L6) { l = 6; rem -= PW_L5; }
    else if (rem < PW_L5 + PW_L6 + PW_L7) { l = 7; rem -= PW_L5 + PW_L6; }
    else return;

    int S = 512 >> l;
    int B = 1 << (l - 1);              // 16 / 32 / 64
    int nbox = B * B;
    int q = rem & 3; int idx = rem >> 2;
    int x = idx % S; idx /= S;
    int y = idx % S;
    int pl = idx / S;

    float4 acc = make_float4(0.f, 0.f, 0.f, 0.f);
    for (int j = lane; j < nbox; j += 32) {
        int by = j / B, bx = j - by * B;
        long e = ((long)(pl * 256 + y * B + by) * 256 + x * B + bx) * 4 + q;
        float4 v = __ldg(l1 + e);
        acc.x += v.x; acc.y += v.y; acc.z += v.z; acc.w += v.w;
    }
    #pragma unroll
    for (int off = 16; off > 0; off >>= 1) {
        acc.x += __shfl_down_sync(0xffffffffu, acc.x, off);
        acc.y += __shfl_down_sync(0xffffffffu, acc.y, off);
        acc.z += __shfl_down_sync(0xffffffffu, acc.z, off);
        acc.w += __shfl_down_sync(0xffffffffu, acc.w, off);
    }
    if (lane == 0) {
        float inv = 1.0f / (float)nbox;
        acc.x *= inv; acc.y *= inv; acc.z *= inv; acc.w *= inv;
        __half2 h0 = __floats2half2_rn(acc.x, acc.y);
        __half2 h1 = __floats2half2_rn(acc.z, acc.w);
        uint2 po; po.x = *(unsigned*)&h0; po.y = *(unsigned*)&h1;
        ((uint2*)(g_pyrh + c_offh[l]))[((long)(pl * S + y) * S + x) * 4 + q] = po;
    }
}

// ---------------------------------------------------------------------------
// Sampler (v2 style): one thread per (point, plane, feature-half).
// 8x 16B __ldg gathers, fp32 math, two coalesced float4 stores.
__global__ void __launch_bounds__(256) trimip_sample(
    const float* __restrict__ x,
    const float* __restrict__ level,
    float* __restrict__ out,
    int N)
{
    int t = blockIdx.x * blockDim.x + threadIdx.x;
    if (t >= N * 6) return;
    int n = t / 6;
    int r = t - n * 6;
    int p = r >> 1;     // plane 0..2
    int h = r & 1;      // feature half (8 feats)

    float xc0 = __ldg(&x[3 * n + 0]);
    float xc1 = __ldg(&x[3 * n + 1]);
    float xc2 = __ldg(&x[3 * n + 2]);
    // plane uv: p0 -> (x1, x2), p1 -> (x0, x2), p2 -> (x0, x1)
    float u = (p == 0) ? xc1 : xc0;   // xx index (uv[...,0])
    float v = (p == 2) ? xc1 : xc2;   // yy index (uv[...,1])

    float lvl = fminf(fmaxf(__ldg(&level[n]), 0.0f), (float)(NLV - 1));
    int   l0  = min((int)lvl, NLV - 2);
    float fr  = lvl - (float)l0;

    float acc[8] = {0.f, 0.f, 0.f, 0.f, 0.f, 0.f, 0.f, 0.f};

    #pragma unroll
    for (int k = 0; k < 2; k++) {
        int   l = l0 + k;
        float w = k ? fr : (1.0f - fr);
        int   S = 512 >> l;

        const __half* base = g_pyrh + c_offh[l] + (long)p * S * S * 16 + h * 8;

        float px = u * (float)S - 0.5f;
        float py = v * (float)S - 0.5f;
        float fx = floorf(px);
        float fy = floorf(py);
        int ix0 = (int)fx;
        int iy0 = (int)fy;
        int ix1 = min(ix0 + 1, S - 1);
        int iy1 = min(iy0 + 1, S - 1);
        ix0 = max(ix0, 0);
        iy0 = max(iy0, 0);
        float ax = px - fx;
        float ay = py - fy;

        float4 v00 = __ldg((const float4*)(base + (iy0 * S + ix0) * 16));
        float4 v10 = __ldg((const float4*)(base + (iy0 * S + ix1) * 16));
        float4 v01 = __ldg((const float4*)(base + (iy1 * S + ix0) * 16));
        float4 v11 = __ldg((const float4*)(base + (iy1 * S + ix1) * 16));

        float w00 = w * (1.0f - ax) * (1.0f - ay);
        float w10 = w * ax * (1.0f - ay);
        float w01 = w * (1.0f - ax) * ay;
        float w11 = w * ax * ay;

        #define ACCQ(wgt, raw) { const __half2* _hp = (const __half2*)&(raw); \
            float2 _f0 = __half22float2(_hp[0]); float2 _f1 = __half22float2(_hp[1]); \
            float2 _f2 = __half22float2(_hp[2]); float2 _f3 = __half22float2(_hp[3]); \
            acc[0] = fmaf(wgt, _f0.x, acc[0]); acc[1] = fmaf(wgt, _f0.y, acc[1]); \
            acc[2] = fmaf(wgt, _f1.x, acc[2]); acc[3] = fmaf(wgt, _f1.y, acc[3]); \
            acc[4] = fmaf(wgt, _f2.x, acc[4]); acc[5] = fmaf(wgt, _f2.y, acc[5]); \
            acc[6] = fmaf(wgt, _f3.x, acc[6]); acc[7] = fmaf(wgt, _f3.y, acc[7]); }
        ACCQ(w00, v00); ACCQ(w10, v10); ACCQ(w01, v01); ACCQ(w11, v11);
        #undef ACCQ
    }

    float4* o = (float4*)(out + (long)n * 48 + p * 16 + h * 8);
    o[0] = make_float4(acc[0], acc[1], acc[2], acc[3]);
    o[1] = make_float4(acc[4], acc[5], acc[6], acc[7]);
}

// ---------------------------------------------------------------------------
extern "C" void kernel_launch(void* const* d_in, const int* in_sizes, int n_in,
                              void* d_out, int out_size) {
    const float* x     = (const float*)d_in[0];
    const float* level = (const float*)d_in[1];
    const float* fm    = (const float*)d_in[2];
    float* out = (float*)d_out;
    int N = in_sizes[0] / 3;

    // K1: level 0 convert + level 1 build (single pass over fm)
    {
        int total = 3 * 256 * 256 * 4;
        k1_l0_l1<<<(total + 255) / 256, 256>>>(fm);
    }
    // K2: levels 2..7
    {
        int total_threads = 258048 + (3072 + 768 + 192) * 32;  // 387072
        k2_levels<<<(total_threads + 255) / 256, 256>>>();
    }
    // S: sampler
    {
        int total = N * 6;
        trimip_sample<<<(total + 255) / 256, 256>>>(x, level, out, N);
    }
}

// round 12
// speedup vs baseline: 1.1406x; 1.0625x over previous
#include <cuda_runtime.h>
#include <cuda_fp16.h>

// TriMip encoding v5: fused 2-kernel build + persistent sampler with
// levels 4..7 (130.5 KB) staged in dynamic shared memory.
//  - levels >=4 fetches: explicit LDS (smem crossbar, offloads L1tex/LTS)
//  - levels <=3 fetches: explicit __ldg (read-only global path)
//  - 1024 threads/block, grid=148 (1 block/SM due to smem), grid-stride.

#define NLV 8

// fp32 level-1 scratch: 3*256*256*16 floats = 12.6 MB
__device__ float g_l1[3145728];
// fp16 pyramid, levels 0..7: 16,776,960 halves (~33.5 MB)
__device__ __half g_pyrh[16776960];

// half offsets of fp16 levels inside g_pyrh
__constant__ int c_offh[8] = {0, 12582912, 15728640, 16515072, 16711680,
                              16760832, 16773120, 16776192};

#define L4_OFF    16711680            // c_offh[4]
#define SMEM_HALVES 65280             // levels 4..7 total halves (130,560 B)

// ---------------------------------------------------------------------------
// K1: one thread per level-1 quad (3*256*256*4 threads).
__global__ void __launch_bounds__(256) k1_l0_l1(const float* __restrict__ fm) {
    int t = blockIdx.x * blockDim.x + threadIdx.x;
    const int total = 3 * 256 * 256 * 4;
    if (t >= total) return;
    int q   = t & 3;
    int idx = t >> 2;
    int xo  = idx & 255; idx >>= 8;
    int yo  = idx & 255;
    int pl  = idx >> 8;

    const float4* src = (const float4*)fm;
    int y0 = 2 * yo, x0 = 2 * xo;
    long b00 = ((long)(pl * 512 + y0) * 512 + x0) * 4 + q;
    float4 a = __ldg(src + b00);
    float4 b = __ldg(src + b00 + 4);
    float4 c = __ldg(src + b00 + 512 * 4);
    float4 d = __ldg(src + b00 + 512 * 4 + 4);

    uint2* l0h = (uint2*)g_pyrh;
    uint2 pa, pb, pc, pd;
    #define PACKQ(dst, v) { __half2 _h0 = __floats2half2_rn((v).x, (v).y); \
                            __half2 _h1 = __floats2half2_rn((v).z, (v).w); \
                            (dst).x = *(unsigned*)&_h0; (dst).y = *(unsigned*)&_h1; }
    PACKQ(pa, a); PACKQ(pb, b); PACKQ(pc, c); PACKQ(pd, d);
    l0h[b00]               = pa;
    l0h[b00 + 4]           = pb;
    l0h[b00 + 512 * 4]     = pc;
    l0h[b00 + 512 * 4 + 4] = pd;

    float4 o;
    o.x = (a.x + b.x + c.x + d.x) * 0.25f;
    o.y = (a.y + b.y + c.y + d.y) * 0.25f;
    o.z = (a.z + b.z + c.z + d.z) * 0.25f;
    o.w = (a.w + b.w + c.w + d.w) * 0.25f;

    long l1i = ((long)(pl * 256 + yo) * 256 + xo) * 4 + q;
    ((float4*)g_l1)[l1i] = o;
    uint2 po; PACKQ(po, o);
    ((uint2*)(g_pyrh + c_offh[1]))[l1i] = po;
    #undef PACKQ
}

// ---------------------------------------------------------------------------
// K2: levels 2..7 from fp32 level1 by flat box mean.
__global__ void __launch_bounds__(256) k2_levels(void) {
    const int PT_L2 = 3 * 128 * 128 * 4;
    const int PT_L3 = 3 * 64 * 64 * 4;
    const int PT_L4 = 3 * 32 * 32 * 4;
    const int PT_TOTAL = PT_L2 + PT_L3 + PT_L4;
    const int PW_L5 = 3 * 16 * 16 * 4;
    const int PW_L6 = 3 * 8 * 8 * 4;
    const int PW_L7 = 3 * 4 * 4 * 4;

    int t = blockIdx.x * blockDim.x + threadIdx.x;
    const float4* l1 = (const float4*)g_l1;

    if (t < PT_TOTAL) {
        int l, rem = t;
        if (rem < PT_L2) l = 2;
        else if (rem < PT_L2 + PT_L3) { l = 3; rem -= PT_L2; }
        else { l = 4; rem -= PT_L2 + PT_L3; }
        int S = 512 >> l;
        int B = 1 << (l - 1);
        int q = rem & 3; int idx = rem >> 2;
        int x = idx % S; idx /= S;
        int y = idx % S;
        int pl = idx / S;

        float4 acc = make_float4(0.f, 0.f, 0.f, 0.f);
        int ybase = y * B, xbase = x * B;
        for (int by = 0; by < B; by++) {
            long row = ((long)(pl * 256 + ybase + by) * 256 + xbase) * 4 + q;
            for (int bx = 0; bx < B; bx++) {
                float4 v = __ldg(l1 + row + bx * 4);
                acc.x += v.x; acc.y += v.y; acc.z += v.z; acc.w += v.w;
            }
        }
        float inv = 1.0f / (float)(B * B);
        acc.x *= inv; acc.y *= inv; acc.z *= inv; acc.w *= inv;
        __half2 h0 = __floats2half2_rn(acc.x, acc.y);
        __half2 h1 = __floats2half2_rn(acc.z, acc.w);
        uint2 po; po.x = *(unsigned*)&h0; po.y = *(unsigned*)&h1;
        ((uint2*)(g_pyrh + c_offh[l]))[((long)(pl * S + y) * S + x) * 4 + q] = po;
        return;
    }

    int w = (t - PT_TOTAL) >> 5;
    int lane = t & 31;
    int l, rem = w;
    if (rem < PW_L5) l = 5;
    else if (rem < PW_L5 + PW_L6) { l = 6; rem -= PW_L5; }
    else if (rem < PW_L5 + PW_L6 + PW_L7) { l = 7; rem -= PW_L5 + PW_L6; }
    else return;

    int S = 512 >> l;
    int B = 1 << (l - 1);
    int nbox = B * B;
    int q = rem & 3; int idx = rem >> 2;
    int x = idx % S; idx /= S;
    int y = idx % S;
    int pl = idx / S;

    float4 acc = make_float4(0.f, 0.f, 0.f, 0.f);
    for (int j = lane; j < nbox; j += 32) {
        int by = j / B, bx = j - by * B;
        long e = ((long)(pl * 256 + y * B + by) * 256 + x * B + bx) * 4 + q;
        float4 v = __ldg(l1 + e);
        acc.x += v.x; acc.y += v.y; acc.z += v.z; acc.w += v.w;
    }
    #pragma unroll
    for (int off = 16; off > 0; off >>= 1) {
        acc.x += __shfl_down_sync(0xffffffffu, acc.x, off);
        acc.y += __shfl_down_sync(0xffffffffu, acc.y, off);
        acc.z += __shfl_down_sync(0xffffffffu, acc.z, off);
        acc.w += __shfl_down_sync(0xffffffffu, acc.w, off);
    }
    if (lane == 0) {
        float inv = 1.0f / (float)nbox;
        acc.x *= inv; acc.y *= inv; acc.z *= inv; acc.w *= inv;
        __half2 h0 = __floats2half2_rn(acc.x, acc.y);
        __half2 h1 = __floats2half2_rn(acc.z, acc.w);
        uint2 po; po.x = *(unsigned*)&h0; po.y = *(unsigned*)&h1;
        ((uint2*)(g_pyrh + c_offh[l]))[((long)(pl * S + y) * S + x) * 4 + q] = po;
    }
}

// ---------------------------------------------------------------------------
// Sampler: persistent, levels 4..7 in dynamic smem, explicit LDS/LDG split.
__global__ void __launch_bounds__(1024, 1) trimip_sample(
    const float* __restrict__ x,
    const float* __restrict__ level,
    float* __restrict__ out,
    int N)
{
    extern __shared__ __align__(16) __half s_top[];   // SMEM_HALVES

    // fill smem with levels 4..7 (contiguous in g_pyrh from L4_OFF)
    {
        const float4* src = (const float4*)(g_pyrh + L4_OFF);
        float4* dst = (float4*)s_top;
        for (int i = threadIdx.x; i < SMEM_HALVES / 8; i += blockDim.x)
            dst[i] = __ldg(src + i);
    }
    __syncthreads();

    int total = N * 6;
    int stride = gridDim.x * blockDim.x;

    for (int t = blockIdx.x * blockDim.x + threadIdx.x; t < total; t += stride) {
        int n = t / 6;
        int r = t - n * 6;
        int p = r >> 1;     // plane 0..2
        int h = r & 1;      // feature half (8 feats)

        float xc0 = __ldg(&x[3 * n + 0]);
        float xc1 = __ldg(&x[3 * n + 1]);
        float xc2 = __ldg(&x[3 * n + 2]);
        float u = (p == 0) ? xc1 : xc0;
        float v = (p == 2) ? xc1 : xc2;

        float lvl = fminf(fmaxf(__ldg(&level[n]), 0.0f), (float)(NLV - 1));
        int   l0  = min((int)lvl, NLV - 2);
        float fr  = lvl - (float)l0;

        float acc[8] = {0.f, 0.f, 0.f, 0.f, 0.f, 0.f, 0.f, 0.f};

        #pragma unroll
        for (int k = 0; k < 2; k++) {
            int   l = l0 + k;
            float w = k ? fr : (1.0f - fr);
            int   S = 512 >> l;

            float px = u * (float)S - 0.5f;
            float py = v * (float)S - 0.5f;
            float fx = floorf(px);
            float fy = floorf(py);
            int ix0 = (int)fx;
            int iy0 = (int)fy;
            int ix1 = min(ix0 + 1, S - 1);
            int iy1 = min(iy0 + 1, S - 1);
            ix0 = max(ix0, 0);
            iy0 = max(iy0, 0);
            float ax = px - fx;
            float ay = py - fy;

            long e00 = (long)(iy0 * S + ix0) * 16;
            long e10 = (long)(iy0 * S + ix1) * 16;
            long e01 = (long)(iy1 * S + ix0) * 16;
            long e11 = (long)(iy1 * S + ix1) * 16;

            float4 v00, v10, v01, v11;
            if (l >= 4) {
                // shared-memory path (explicit LDS)
                const __half* b = s_top + (c_offh[l] - L4_OFF)
                                + (long)p * S * S * 16 + h * 8;
                v00 = *(const float4*)(b + e00);
                v10 = *(const float4*)(b + e10);
                v01 = *(const float4*)(b + e01);
                v11 = *(const float4*)(b + e11);
            } else {
                // global read-only path (explicit LDG.nc)
                const __half* b = g_pyrh + c_offh[l]
                                + (long)p * S * S * 16 + h * 8;
                v00 = __ldg((const float4*)(b + e00));
                v10 = __ldg((const float4*)(b + e10));
                v01 = __ldg((const float4*)(b + e01));
                v11 = __ldg((const float4*)(b + e11));
            }

            float w00 = w * (1.0f - ax) * (1.0f - ay);
            float w10 = w * ax * (1.0f - ay);
            float w01 = w * (1.0f - ax) * ay;
            float w11 = w * ax * ay;

            #define ACCQ(wgt, raw) { const __half2* _hp = (const __half2*)&(raw); \
                float2 _f0 = __half22float2(_hp[0]); float2 _f1 = __half22float2(_hp[1]); \
                float2 _f2 = __half22float2(_hp[2]); float2 _f3 = __half22float2(_hp[3]); \
                acc[0] = fmaf(wgt, _f0.x, acc[0]); acc[1] = fmaf(wgt, _f0.y, acc[1]); \
                acc[2] = fmaf(wgt, _f1.x, acc[2]); acc[3] = fmaf(wgt, _f1.y, acc[3]); \
                acc[4] = fmaf(wgt, _f2.x, acc[4]); acc[5] = fmaf(wgt, _f2.y, acc[5]); \
                acc[6] = fmaf(wgt, _f3.x, acc[6]); acc[7] = fmaf(wgt, _f3.y, acc[7]); }
            ACCQ(w00, v00); ACCQ(w10, v10); ACCQ(w01, v01); ACCQ(w11, v11);
            #undef ACCQ
        }

        float4* o = (float4*)(out + (long)n * 48 + p * 16 + h * 8);
        o[0] = make_float4(acc[0], acc[1], acc[2], acc[3]);
        o[1] = make_float4(acc[4], acc[5], acc[6], acc[7]);
    }
}

// ---------------------------------------------------------------------------
extern "C" void kernel_launch(void* const* d_in, const int* in_sizes, int n_in,
                              void* d_out, int out_size) {
    const float* x     = (const float*)d_in[0];
    const float* level = (const float*)d_in[1];
    const float* fm    = (const float*)d_in[2];
    float* out = (float*)d_out;
    int N = in_sizes[0] / 3;

    // K1: level 0 convert + level 1 build
    {
        int total = 3 * 256 * 256 * 4;
        k1_l0_l1<<<(total + 255) / 256, 256>>>(fm);
    }
    // K2: levels 2..7
    {
        int total_threads = 258048 + (3072 + 768 + 192) * 32;
        k2_levels<<<(total_threads + 255) / 256, 256>>>();
    }
    // S: persistent sampler, 130.5 KB dynamic smem
    {
        const int smem_bytes = SMEM_HALVES * 2;   // 130,560
        cudaFuncSetAttribute(trimip_sample,
                             cudaFuncAttributeMaxDynamicSharedMemorySize,
                             smem_bytes);
        trimip_sample<<<148, 1024, smem_bytes>>>(x, level, out, N);
    }
}